// round 3
// baseline (speedup 1.0000x reference)
#include <cuda_runtime.h>
#include <math.h>

#define N_NODES   15000
#define N_EDGES   60000
#define EDGE_VOCAB 54
#define NODE_INDIM 64
#define EDGE_INDIM 32
#define H  32
#define EH 64
#define NBOND 4
#define NUM_STEPS 3
#define EPB 64   // edges per block in the grouped edge kernel

// ---------------- scratch (device globals: no allocation allowed) ----------
__device__ float g_Wv[EDGE_VOCAB * H * H];   // 54 per-vocab edge weight matrices
__device__ float g_h[N_NODES * H];           // node hidden state
__device__ float g_agg[N_NODES * H];         // unnormalized weighted message sum
__device__ float g_p[N_NODES];               // h . attn_w[:H]
__device__ float g_q[N_NODES];               // h . attn_w[H:]
__device__ float g_nsum[N_NODES];            // segment sum of exp(logit)
__device__ int   g_cnt[EDGE_VOCAB];          // histogram
__device__ int   g_cur[EDGE_VOCAB];          // scatter cursors
__device__ int   g_order[N_EDGES];           // edges sorted by edge_id

// ---------------- 0) per-vocab edge weight matrices (54 of them) -----------
__global__ void k_wvocab(const float* __restrict__ edge_table,
                         const float* __restrict__ e1W1, const float* __restrict__ e1b1,
                         const float* __restrict__ e1W2, const float* __restrict__ e1b2,
                         const float* __restrict__ e2W1, const float* __restrict__ e2b1,
                         const float* __restrict__ e2W2, const float* __restrict__ e2b2) {
    int v = blockIdx.x;
    int t = threadIdx.x;                       // 256 threads
    if (v == 0 && t < EDGE_VOCAB) g_cnt[t] = 0;   // fold histogram zeroing in here
    bool bond = (v < NBOND);
    const float* W1 = bond ? e1W1 : e2W1;
    const float* b1 = bond ? e1b1 : e2b1;
    const float* W2 = bond ? e1W2 : e2W2;
    const float* b2 = bond ? e1b2 : e2b2;

    __shared__ float ef[EDGE_INDIM];
    __shared__ float z[EH];
    if (t < EDGE_INDIM) ef[t] = edge_table[v * EDGE_INDIM + t];
    __syncthreads();
    if (t < EH) {
        float acc = b1[t];
        #pragma unroll
        for (int i = 0; i < EDGE_INDIM; i++) acc += ef[i] * W1[t * EDGE_INDIM + i];
        z[t] = fmaxf(acc, 0.0f);
    }
    __syncthreads();
    for (int o = t; o < H * H; o += blockDim.x) {
        float acc = b2[o];
        const float* w = W2 + o * EH;
        #pragma unroll
        for (int k = 0; k < EH; k++) acc += z[k] * w[k];
        g_Wv[v * H * H + o] = acc;
    }
}

// ---------------- sort edges by vocab id (counting sort, 3 tiny kernels) ---
__global__ void k_hist(const int* __restrict__ eids) {
    int e = blockIdx.x * blockDim.x + threadIdx.x;
    if (e < N_EDGES) atomicAdd(&g_cnt[eids[e]], 1);
}
__global__ void k_scan() {
    if (threadIdx.x == 0) {
        int acc = 0;
        for (int v = 0; v < EDGE_VOCAB; v++) { g_cur[v] = acc; acc += g_cnt[v]; }
    }
}
__global__ void k_scatter(const int* __restrict__ eids) {
    int e = blockIdx.x * blockDim.x + threadIdx.x;
    if (e < N_EDGES) {
        int pos = atomicAdd(&g_cur[eids[e]], 1);
        g_order[pos] = e;
    }
}

// ---------------- 1) initial projection + attention dots + reset -----------
__global__ void k_init_h(const int* __restrict__ node_ids,
                         const float* __restrict__ node_table,
                         const float* __restrict__ projW,
                         const float* __restrict__ projb,
                         const float* __restrict__ attn_w) {
    __shared__ float sW[NODE_INDIM * H];       // transposed: sW[i*H + o]
    int t = threadIdx.x;
    for (int idx = t; idx < H * NODE_INDIM; idx += blockDim.x) {
        int o = idx / NODE_INDIM, i = idx % NODE_INDIM;
        sW[i * H + o] = projW[idx];
    }
    __syncthreads();
    int gt = blockIdx.x * blockDim.x + t;
    int node = gt >> 5, lane = gt & 31;
    if (node >= N_NODES) return;
    int nid = node_ids[node];
    const float* nf = node_table + nid * NODE_INDIM;
    float v0 = nf[lane];
    float v1 = nf[lane + 32];
    float acc = projb[lane];
    #pragma unroll
    for (int i = 0; i < 32; i++)
        acc += __shfl_sync(0xffffffffu, v0, i) * sW[i * H + lane];
    #pragma unroll
    for (int i = 0; i < 32; i++)
        acc += __shfl_sync(0xffffffffu, v1, i) * sW[(i + 32) * H + lane];
    float hv = fmaxf(acc, 0.0f);
    g_h[node * H + lane] = hv;
    g_agg[node * H + lane] = 0.0f;
    // attention dots
    float pv = hv * attn_w[lane];
    float qv = hv * attn_w[H + lane];
    #pragma unroll
    for (int off = 16; off; off >>= 1) {
        pv += __shfl_down_sync(0xffffffffu, pv, off);
        qv += __shfl_down_sync(0xffffffffu, qv, off);
    }
    if (lane == 0) { g_p[node] = pv; g_q[node] = qv; g_nsum[node] = 0.0f; }
}

// ---------------- 2) heavy edge kernel: W cached in smem per block ---------
__global__ void __launch_bounds__(256) k_edge_msg(const int* __restrict__ src,
                                                  const int* __restrict__ dst,
                                                  const int* __restrict__ eids) {
    __shared__ float sW[H * H];
    __shared__ int sId;
    int t = threadIdx.x, w = t >> 5, lane = t & 31;
    int base = blockIdx.x * EPB;
    if (t == 0) sId = eids[g_order[base]];
    __syncthreads();
    int id0 = sId;
    // cooperative 4 KB W load (float4)
    {
        const float4* Wsrc = (const float4*)(g_Wv + id0 * H * H);
        ((float4*)sW)[t] = Wsrc[t];
    }
    __syncthreads();

    #pragma unroll
    for (int i = 0; i < EPB / 8; i++) {
        int pos = base + w * (EPB / 8) + i;
        if (pos >= N_EDGES) break;
        int e = g_order[pos];
        int s = src[e], d = dst[e], id = eids[e];
        float a = g_p[s] + g_q[d];
        a = (a > 0.0f) ? a : 0.01f * a;            // leaky_relu
        float ex = expf(a);                        // softmax shift-invariant: no max pass
        float hv = g_h[s * H + lane];
        float acc = 0.0f;
        if (id == id0) {
            #pragma unroll
            for (int k = 0; k < H; k++)
                acc += __shfl_sync(0xffffffffu, hv, k) * sW[k * H + lane];
        } else {  // rare: block straddles a bucket boundary
            const float* __restrict__ W = g_Wv + id * H * H;
            #pragma unroll
            for (int k = 0; k < H; k++)
                acc += __shfl_sync(0xffffffffu, hv, k) * W[k * H + lane];
        }
        acc *= ex;
        // pack 4 lanes -> one red.global.add.v4.f32
        float a1 = __shfl_down_sync(0xffffffffu, acc, 1);
        float a2 = __shfl_down_sync(0xffffffffu, acc, 2);
        float a3 = __shfl_down_sync(0xffffffffu, acc, 3);
        if ((lane & 3) == 0) {
            float* addr = g_agg + d * H + lane;
            asm volatile("red.global.add.v4.f32 [%0], {%1,%2,%3,%4};"
                         :: "l"(addr), "f"(acc), "f"(a1), "f"(a2), "f"(a3)
                         : "memory");
        }
        if (lane == 0) atomicAdd(&g_nsum[d], ex);
    }
}

// ---------------- 3) normalize + relu + GRU + next-step prep ---------------
__global__ void k_gru(const float* __restrict__ Wih, const float* __restrict__ Whh,
                      const float* __restrict__ bih, const float* __restrict__ bhh,
                      const float* __restrict__ attn_w,
                      float* __restrict__ out, int writeOut) {
    __shared__ float sWihT[H * 3 * H];         // [i*96 + o]
    __shared__ float sWhhT[H * 3 * H];
    int t = threadIdx.x;
    for (int idx = t; idx < 3 * H * H; idx += blockDim.x) {
        int o = idx / H, i = idx % H;
        sWihT[i * 96 + o] = Wih[idx];
        sWhhT[i * 96 + o] = Whh[idx];
    }
    __syncthreads();
    int gt = blockIdx.x * blockDim.x + t;
    int v = gt >> 5, lane = gt & 31;
    if (v >= N_NODES) return;
    float ns = g_nsum[v];
    float inv = (ns > 0.0f) ? (1.0f / ns) : 0.0f;   // isolated nodes -> m = 0
    float m  = fmaxf(g_agg[v * H + lane] * inv, 0.0f);
    float hv = g_h[v * H + lane];
    float gi0 = bih[lane], gi1 = bih[32 + lane], gi2 = bih[64 + lane];
    float gh0 = bhh[lane], gh1 = bhh[32 + lane], gh2 = bhh[64 + lane];
    #pragma unroll
    for (int i = 0; i < H; i++) {
        float mi = __shfl_sync(0xffffffffu, m, i);
        float hi = __shfl_sync(0xffffffffu, hv, i);
        gi0 += mi * sWihT[i * 96 + lane];
        gi1 += mi * sWihT[i * 96 + 32 + lane];
        gi2 += mi * sWihT[i * 96 + 64 + lane];
        gh0 += hi * sWhhT[i * 96 + lane];
        gh1 += hi * sWhhT[i * 96 + 32 + lane];
        gh2 += hi * sWhhT[i * 96 + 64 + lane];
    }
    float r = 1.0f / (1.0f + expf(-(gi0 + gh0)));
    float z = 1.0f / (1.0f + expf(-(gi1 + gh1)));
    float n = tanhf(gi2 + r * gh2);
    float hnew = (1.0f - z) * n + z * hv;
    g_h[v * H + lane] = hnew;
    if (writeOut) out[v * H + lane] = hnew;
    // prep next step: attention dots + accumulator reset
    g_agg[v * H + lane] = 0.0f;
    float pv = hnew * attn_w[lane];
    float qv = hnew * attn_w[H + lane];
    #pragma unroll
    for (int off = 16; off; off >>= 1) {
        pv += __shfl_down_sync(0xffffffffu, pv, off);
        qv += __shfl_down_sync(0xffffffffu, qv, off);
    }
    if (lane == 0) { g_p[v] = pv; g_q[v] = qv; g_nsum[v] = 0.0f; }
}

// ---------------- launch ----------------------------------------------------
extern "C" void kernel_launch(void* const* d_in, const int* in_sizes, int n_in,
                              void* d_out, int out_size) {
    const int*   node_ids   = (const int*)  d_in[0];
    const int*   edge_ids   = (const int*)  d_in[1];
    const int*   src        = (const int*)  d_in[2];
    const int*   dst        = (const int*)  d_in[3];
    const float* node_table = (const float*)d_in[4];
    const float* edge_table = (const float*)d_in[5];
    const float* proj_W     = (const float*)d_in[6];
    const float* proj_b     = (const float*)d_in[7];
    const float* attn_w     = (const float*)d_in[8];
    const float* e1_W1      = (const float*)d_in[9];
    const float* e1_b1      = (const float*)d_in[10];
    const float* e1_W2      = (const float*)d_in[11];
    const float* e1_b2      = (const float*)d_in[12];
    const float* e2_W1      = (const float*)d_in[13];
    const float* e2_b1      = (const float*)d_in[14];
    const float* e2_W2      = (const float*)d_in[15];
    const float* e2_b2      = (const float*)d_in[16];
    const float* gru_Wih    = (const float*)d_in[17];
    const float* gru_Whh    = (const float*)d_in[18];
    const float* gru_bih    = (const float*)d_in[19];
    const float* gru_bhh    = (const float*)d_in[20];
    float* out = (float*)d_out;

    const int NODE_WARP_BLOCKS = (N_NODES * 32 + 255) / 256;   // warp per node
    const int EDGE_THR_BLOCKS  = (N_EDGES + 255) / 256;        // thread per edge
    const int EDGE_MSG_BLOCKS  = (N_EDGES + EPB - 1) / EPB;    // EPB edges / block

    k_wvocab<<<EDGE_VOCAB, 256>>>(edge_table, e1_W1, e1_b1, e1_W2, e1_b2,
                                  e2_W1, e2_b1, e2_W2, e2_b2);
    k_hist<<<EDGE_THR_BLOCKS, 256>>>(edge_ids);
    k_scan<<<1, 32>>>();
    k_scatter<<<EDGE_THR_BLOCKS, 256>>>(edge_ids);
    k_init_h<<<NODE_WARP_BLOCKS, 256>>>(node_ids, node_table, proj_W, proj_b, attn_w);

    for (int step = 0; step < NUM_STEPS; step++) {
        k_edge_msg<<<EDGE_MSG_BLOCKS, 256>>>(src, dst, edge_ids);
        k_gru<<<NODE_WARP_BLOCKS, 256>>>(gru_Wih, gru_Whh, gru_bih, gru_bhh,
                                         attn_w, out, step == NUM_STEPS - 1 ? 1 : 0);
    }
}

// round 4
// speedup vs baseline: 1.6113x; 1.6113x over previous
#include <cuda_runtime.h>
#include <math.h>

#define N_NODES   15000
#define N_EDGES   60000
#define EDGE_VOCAB 54
#define NODE_INDIM 64
#define EDGE_INDIM 32
#define H  32
#define EH 64
#define NBOND 4
#define NUM_STEPS 3
#define G   148                    // persistent blocks (<= SM count, 1/SM)
#define TPB 512
#define WPB (TPB / 32)
#define NWARPS (G * WPB)
#define CHUNK ((N_EDGES + G - 1) / G)

// ---------------- device scratch (no allocation allowed) -------------------
__device__ __align__(16) float g_Wv[EDGE_VOCAB * H * H];
__device__ __align__(16) float g_h[N_NODES * H];
__device__ __align__(16) float g_agg[N_NODES * H];
__device__ float g_p[N_NODES];
__device__ float g_q[N_NODES];
__device__ float g_nsum[N_NODES];
__device__ int   g_blockcnt[G * 64];
__device__ int   g_boff[G * 64];
__device__ int   g_e1[N_EDGES];       // src | (edge_id << 16), sorted by edge_id
__device__ int   g_e2[N_EDGES];       // dst, sorted by edge_id
__device__ int           g_bar_count = 0;
__device__ volatile int  g_bar_sense = 0;

// sense-reversing grid barrier. Must be called an EVEN number of times per
// kernel so g_bar_sense returns to 0 for the next launch/replay.
__device__ __forceinline__ void grid_barrier(int* bsense) {
    __syncthreads();
    if (threadIdx.x == 0) {
        int my = *bsense ^ 1;
        __threadfence();
        if (atomicAdd(&g_bar_count, 1) == G - 1) {
            g_bar_count = 0;
            __threadfence();
            g_bar_sense = my;
        } else {
            while (g_bar_sense != my) { __nanosleep(32); }
        }
        __threadfence();
        *bsense = my;
    }
    __syncthreads();
}

__global__ void __launch_bounds__(TPB, 1)
k_fused(const int* __restrict__ node_ids, const int* __restrict__ edge_ids,
        const int* __restrict__ src, const int* __restrict__ dst,
        const float* __restrict__ node_table, const float* __restrict__ edge_table,
        const float* __restrict__ projW, const float* __restrict__ projb,
        const float* __restrict__ attn_w,
        const float* __restrict__ e1W1, const float* __restrict__ e1b1,
        const float* __restrict__ e1W2, const float* __restrict__ e1b2,
        const float* __restrict__ e2W1, const float* __restrict__ e2b1,
        const float* __restrict__ e2W2, const float* __restrict__ e2b2,
        const float* __restrict__ Wih, const float* __restrict__ Whh,
        const float* __restrict__ bih, const float* __restrict__ bhh,
        float* __restrict__ out) {
    __shared__ float S[2 * 3 * H * H];     // 6144 floats = 24 KB, reused per phase
    __shared__ int   SI[64];
    __shared__ int   bsense;

    const int t    = threadIdx.x;
    const int b    = blockIdx.x;
    const int warp = t >> 5;
    const int lane = t & 31;
    const int gwarp = b * WPB + warp;

    if (t == 0) bsense = 0;
    __syncthreads();

    const int ebase = b * CHUNK;
    const int eend  = min(ebase + CHUNK, N_EDGES);

    // ================= phase 0: per-block histogram + vocab W matrices =====
    if (t < EDGE_VOCAB) SI[t] = 0;
    __syncthreads();
    for (int e = ebase + t; e < eend; e += TPB) atomicAdd(&SI[edge_ids[e]], 1);
    __syncthreads();
    if (t < EDGE_VOCAB) g_blockcnt[b * 64 + t] = SI[t];

    if (b < EDGE_VOCAB) {   // one block per vocab entry computes its W matrix
        const int v = b;
        const bool bond = (v < NBOND);
        const float* W1 = bond ? e1W1 : e2W1;
        const float* b1 = bond ? e1b1 : e2b1;
        const float* W2 = bond ? e1W2 : e2W2;
        const float* b2 = bond ? e1b2 : e2b2;
        float* ef = S;          // [32]
        float* z  = S + 32;     // [64]
        if (t < EDGE_INDIM) ef[t] = edge_table[v * EDGE_INDIM + t];
        __syncthreads();
        if (t < EH) {
            float acc = b1[t];
            #pragma unroll
            for (int i = 0; i < EDGE_INDIM; i++) acc += ef[i] * W1[t * EDGE_INDIM + i];
            z[t] = fmaxf(acc, 0.0f);
        }
        __syncthreads();
        for (int o = t; o < H * H; o += TPB) {
            float acc = b2[o];
            const float* w = W2 + o * EH;
            #pragma unroll
            for (int k = 0; k < EH; k++) acc += z[k] * w[k];
            g_Wv[v * H * H + o] = acc;
        }
    }
    grid_barrier(&bsense);                                     // B1

    // ================= phase 1: offsets scan (block 0 only) ================
    if (b == 0) {
        if (t < EDGE_VOCAB) {
            int tot = 0;
            for (int bb = 0; bb < G; bb++) tot += g_blockcnt[bb * 64 + t];
            SI[t] = tot;
        }
        __syncthreads();
        if (t == 0) {
            int acc = 0;
            for (int v = 0; v < EDGE_VOCAB; v++) { int c = SI[v]; SI[v] = acc; acc += c; }
        }
        __syncthreads();
        if (t < EDGE_VOCAB) {
            int run = SI[t];
            for (int bb = 0; bb < G; bb++) {
                g_boff[bb * 64 + t] = run;
                run += g_blockcnt[bb * 64 + t];
            }
        }
    }
    grid_barrier(&bsense);                                     // B2

    // ================= phase 2: scatter (sort by vocab) + init h ===========
    if (t < EDGE_VOCAB) SI[t] = g_boff[b * 64 + t];
    __syncthreads();
    for (int e = ebase + t; e < eend; e += TPB) {
        int id = edge_ids[e];
        int pos = atomicAdd(&SI[id], 1);
        g_e1[pos] = src[e] | (id << 16);
        g_e2[pos] = dst[e];
    }
    // init h = relu(nf @ projW^T + b), attention dots, accumulator reset
    {
        for (int idx = t; idx < H * NODE_INDIM; idx += TPB) {
            int o = idx / NODE_INDIM, i = idx % NODE_INDIM;
            S[i * H + o] = projW[idx];      // transposed proj weights
        }
        __syncthreads();
        for (int v = gwarp; v < N_NODES; v += NWARPS) {
            int nid = node_ids[v];
            const float* nf = node_table + nid * NODE_INDIM;
            float v0 = nf[lane];
            float v1 = nf[lane + 32];
            float acc = projb[lane];
            #pragma unroll
            for (int i = 0; i < 32; i++)
                acc += __shfl_sync(0xffffffffu, v0, i) * S[i * H + lane];
            #pragma unroll
            for (int i = 0; i < 32; i++)
                acc += __shfl_sync(0xffffffffu, v1, i) * S[(i + 32) * H + lane];
            float hv = fmaxf(acc, 0.0f);
            g_h[v * H + lane] = hv;
            g_agg[v * H + lane] = 0.0f;
            float pv = hv * attn_w[lane];
            float qv = hv * attn_w[H + lane];
            #pragma unroll
            for (int off = 16; off; off >>= 1) {
                pv += __shfl_down_sync(0xffffffffu, pv, off);
                qv += __shfl_down_sync(0xffffffffu, qv, off);
            }
            if (lane == 0) { g_p[v] = pv; g_q[v] = qv; g_nsum[v] = 0.0f; }
        }
    }
    grid_barrier(&bsense);                                     // B3

    // ================= message passing steps ===============================
    for (int step = 0; step < NUM_STEPS; step++) {
        // ---- edge phase: block handles its sorted chunk, W cached in smem
        int id0 = -1, id1 = -1;
        if (ebase < eend) {
            id0 = g_e1[ebase] >> 16;
            id1 = g_e1[eend - 1] >> 16;
            for (int i = t; i < H * H; i += TPB) S[i] = g_Wv[id0 * H * H + i];
            if (id1 != id0)
                for (int i = t; i < H * H; i += TPB) S[H * H + i] = g_Wv[id1 * H * H + i];
        }
        __syncthreads();
        if (ebase < eend) {
            int len = eend - ebase;
            int per = (len + WPB - 1) / WPB;
            int w0 = ebase + warp * per;
            int w1 = min(w0 + per, eend);
            for (int pos = w0; pos < w1; pos++) {
                int e1 = g_e1[pos], d = g_e2[pos];
                int s = e1 & 0xFFFF, id = e1 >> 16;
                float a = g_p[s] + g_q[d];
                a = (a > 0.0f) ? a : 0.01f * a;            // leaky_relu
                float ex = expf(a);                        // shift-free softmax
                float hv = g_h[s * H + lane];
                float acc = 0.0f;
                if (id == id0 || id == id1) {
                    const float* Ws = (id == id0) ? S : (S + H * H);
                    #pragma unroll
                    for (int k = 0; k < H; k++)
                        acc += __shfl_sync(0xffffffffu, hv, k) * Ws[k * H + lane];
                } else {   // rare: chunk spans >2 vocab buckets
                    const float* Wg = g_Wv + id * H * H;
                    #pragma unroll
                    for (int k = 0; k < H; k++)
                        acc += __shfl_sync(0xffffffffu, hv, k) * Wg[k * H + lane];
                }
                acc *= ex;
                float a1 = __shfl_down_sync(0xffffffffu, acc, 1);
                float a2 = __shfl_down_sync(0xffffffffu, acc, 2);
                float a3 = __shfl_down_sync(0xffffffffu, acc, 3);
                if ((lane & 3) == 0) {
                    float* addr = g_agg + d * H + lane;
                    asm volatile("red.global.add.v4.f32 [%0], {%1,%2,%3,%4};"
                                 :: "l"(addr), "f"(acc), "f"(a1), "f"(a2), "f"(a3)
                                 : "memory");
                }
                if (lane == 0) atomicAdd(&g_nsum[d], ex);
            }
        }
        grid_barrier(&bsense);                                 // B-edge (x3)

        // ---- GRU phase: normalize + relu + GRU + next-step prep
        for (int idx = t; idx < 3 * H * H; idx += TPB) {
            int o = idx / H, i = idx % H;
            S[i * 96 + o] = Wih[idx];
            S[3 * H * H + i * 96 + o] = Whh[idx];
        }
        __syncthreads();
        const float* sWihT = S;
        const float* sWhhT = S + 3 * H * H;
        const int last = (step == NUM_STEPS - 1);
        for (int v = gwarp; v < N_NODES; v += NWARPS) {
            float ns = g_nsum[v];
            float inv = (ns > 0.0f) ? (1.0f / ns) : 0.0f;
            float m  = fmaxf(g_agg[v * H + lane] * inv, 0.0f);
            float hv = g_h[v * H + lane];
            float gi0 = bih[lane], gi1 = bih[32 + lane], gi2 = bih[64 + lane];
            float gh0 = bhh[lane], gh1 = bhh[32 + lane], gh2 = bhh[64 + lane];
            #pragma unroll
            for (int i = 0; i < H; i++) {
                float mi = __shfl_sync(0xffffffffu, m, i);
                float hi = __shfl_sync(0xffffffffu, hv, i);
                gi0 += mi * sWihT[i * 96 + lane];
                gi1 += mi * sWihT[i * 96 + 32 + lane];
                gi2 += mi * sWihT[i * 96 + 64 + lane];
                gh0 += hi * sWhhT[i * 96 + lane];
                gh1 += hi * sWhhT[i * 96 + 32 + lane];
                gh2 += hi * sWhhT[i * 96 + 64 + lane];
            }
            float r = 1.0f / (1.0f + expf(-(gi0 + gh0)));
            float z = 1.0f / (1.0f + expf(-(gi1 + gh1)));
            float n = tanhf(gi2 + r * gh2);
            float hnew = (1.0f - z) * n + z * hv;
            g_h[v * H + lane] = hnew;
            if (last) {
                out[v * H + lane] = hnew;
            } else {
                g_agg[v * H + lane] = 0.0f;
                float pv = hnew * attn_w[lane];
                float qv = hnew * attn_w[H + lane];
                #pragma unroll
                for (int off = 16; off; off >>= 1) {
                    pv += __shfl_down_sync(0xffffffffu, pv, off);
                    qv += __shfl_down_sync(0xffffffffu, qv, off);
                }
                if (lane == 0) { g_p[v] = pv; g_q[v] = qv; g_nsum[v] = 0.0f; }
            }
        }
        if (step < NUM_STEPS - 1) grid_barrier(&bsense);       // B-gru (x2)
    }
    // barriers per call: 3 + 3 + 2 = 8 (even) -> sense back to 0 for replay
}

// ---------------- launch ----------------------------------------------------
extern "C" void kernel_launch(void* const* d_in, const int* in_sizes, int n_in,
                              void* d_out, int out_size) {
    k_fused<<<G, TPB>>>(
        (const int*)d_in[0], (const int*)d_in[1], (const int*)d_in[2],
        (const int*)d_in[3], (const float*)d_in[4], (const float*)d_in[5],
        (const float*)d_in[6], (const float*)d_in[7], (const float*)d_in[8],
        (const float*)d_in[9], (const float*)d_in[10], (const float*)d_in[11],
        (const float*)d_in[12], (const float*)d_in[13], (const float*)d_in[14],
        (const float*)d_in[15], (const float*)d_in[16], (const float*)d_in[17],
        (const float*)d_in[18], (const float*)d_in[19], (const float*)d_in[20],
        (float*)d_out);
}